// round 2
// baseline (speedup 1.0000x reference)
#include <cuda_runtime.h>
#include <math.h>

// Problem constants
static constexpr int S   = 1024;
static constexpr int H   = 2880;
static constexpr int NH  = 64;
static constexpr int NKV = 8;
static constexpr int HD  = 64;
static constexpr int QKV_N = (NH + 2 * NKV) * HD;   // 5120
static constexpr int OD    = NH * HD;               // 4096

// Scratch (allocation-free rule: __device__ globals)
__device__ __align__(16) float g_qkv [S * QKV_N];   // 20 MB
__device__ __align__(16) float g_attn[S * OD];      // 16 MB

// ---------------------------------------------------------------------------
// Generic SGEMM:  C[M,N] = A[M,K] @ B[N,K]^T   (A row-major, B row-major K-last)
// 128x128 block tile, BK=8, 256 threads, 8x8 per-thread micro-tile.
// Requires: M % 128 == 0, K % 8 == 0. N guarded.
// ---------------------------------------------------------------------------
__global__ __launch_bounds__(256, 2) void sgemm_nt(
    const float* __restrict__ A, const float* __restrict__ B,
    float* __restrict__ C, int M, int N, int K)
{
    __shared__ float As[8][128];
    __shared__ float Bs[8][128];

    const int t  = threadIdx.x;
    const int bm = blockIdx.y * 128;
    const int bn = blockIdx.x * 128;

    const int lr = t >> 1;             // 0..127
    const int lc = (t & 1) << 2;       // 0 or 4

    const float* Aptr = A + (size_t)(bm + lr) * K + lc;
    const float* Bptr = B + (size_t)(bn + lr) * K + lc;
    const bool bvalid = (bn + lr) < N;

    const int rm = (t >> 4) << 2;      // 0,4,...,60
    const int rn = (t & 15) << 2;      // 0,4,...,60

    float acc[8][8];
#pragma unroll
    for (int i = 0; i < 8; ++i)
#pragma unroll
        for (int j = 0; j < 8; ++j) acc[i][j] = 0.f;

    for (int kt = 0; kt < K; kt += 8) {
        float4 av = *(const float4*)(Aptr + kt);
        float4 bv = make_float4(0.f, 0.f, 0.f, 0.f);
        if (bvalid) bv = *(const float4*)(Bptr + kt);

        __syncthreads();
        As[lc + 0][lr] = av.x; As[lc + 1][lr] = av.y;
        As[lc + 2][lr] = av.z; As[lc + 3][lr] = av.w;
        Bs[lc + 0][lr] = bv.x; Bs[lc + 1][lr] = bv.y;
        Bs[lc + 2][lr] = bv.z; Bs[lc + 3][lr] = bv.w;
        __syncthreads();

#pragma unroll
        for (int k = 0; k < 8; ++k) {
            float a[8], b[8];
            *(float4*)(a)     = *(const float4*)&As[k][rm];
            *(float4*)(a + 4) = *(const float4*)&As[k][rm + 64];
            *(float4*)(b)     = *(const float4*)&Bs[k][rn];
            *(float4*)(b + 4) = *(const float4*)&Bs[k][rn + 64];
#pragma unroll
            for (int i = 0; i < 8; ++i)
#pragma unroll
                for (int j = 0; j < 8; ++j)
                    acc[i][j] += a[i] * b[j];
        }
    }

#pragma unroll
    for (int ih = 0; ih < 2; ++ih)
#pragma unroll
        for (int ii = 0; ii < 4; ++ii) {
            const int i   = ih * 4 + ii;
            const int row = bm + ih * 64 + rm + ii;
#pragma unroll
            for (int jh = 0; jh < 2; ++jh) {
                const int col = bn + jh * 64 + rn;
                if (col < N) {
                    float4 v = make_float4(acc[i][jh*4+0], acc[i][jh*4+1],
                                           acc[i][jh*4+2], acc[i][jh*4+3]);
                    *(float4*)(C + (size_t)row * N + col) = v;
                }
            }
        }
}

// ---------------------------------------------------------------------------
// RoPE on q (heads 0..63) and k (heads 64..71), in place in g_qkv.
// cos/sin evaluated in double on the fp32 angle (matches reference fp32 angle
// quantization while keeping trig error negligible).
// ---------------------------------------------------------------------------
__global__ void rope_kernel(float* __restrict__ qkv, const int* __restrict__ positions)
{
    const int id = blockIdx.x * blockDim.x + threadIdx.x;
    const int total = S * (NH + NKV) * (HD / 2);
    if (id >= total) return;

    const int p    = id & 31;                 // pair index 0..31
    const int head = (id >> 5) % (NH + NKV);  // 0..71
    const int s    = id / (32 * (NH + NKV));

    const int col = (head < NH) ? head * HD : NH * HD + (head - NH) * HD;
    float* base = qkv + (size_t)s * QKV_N + col;

    const float x1 = base[p];
    const float x2 = base[p + 32];

    const float freq = 1.0f / powf(10000.0f, (float)p * (1.0f / 32.0f));
    const float ang  = (float)positions[s] * freq;
    double sd, cd;
    sincos((double)ang, &sd, &cd);
    const float c = (float)cd, sn = (float)sd;

    base[p]      = x1 * c - x2 * sn;
    base[p + 32] = x2 * c + x1 * sn;
}

// ---------------------------------------------------------------------------
// Flash attention with sink + causal mask.
// grid = (S/64 query tiles, NH heads), 256 threads.
// Per block: 64 queries x 1 head, iterate 64-key tiles up to the diagonal.
// Thread (tq = t>>4, tn = t&15) owns 4 query rows; tn indexes 4 keys in the
// score phase and 4 output dims in the PV phase. P tile aliases the K buffer.
// K tile is XOR-swizzled to avoid stride-256B bank conflicts.
// ---------------------------------------------------------------------------
__global__ __launch_bounds__(256) void attn_kernel(
    const float* __restrict__ qkv, const float* __restrict__ sinks,
    float* __restrict__ obuf)
{
    __shared__ float Qs[64 * 64];
    __shared__ float Ks[64 * 64];   // aliased as P after the score phase
    __shared__ float Vs[64 * 64];

    const int t   = threadIdx.x;
    const int qt  = blockIdx.x;      // query tile 0..15
    const int h   = blockIdx.y;      // head 0..63
    const int kvh = h >> 3;          // kv head = h / G, G = 8
    const int q0  = qt << 6;
    const int tq  = t >> 4;          // 0..15
    const int tn  = t & 15;          // 0..15

    const int qcol = h << 6;
    const int kcol = NH * HD + (kvh << 6);            // 4096 + ...
    const int vcol = NH * HD + NKV * HD + (kvh << 6); // 4608 + ...

    // Load Q tile (linear layout; reads are broadcast so no swizzle needed)
#pragma unroll
    for (int it = 0; it < 4; ++it) {
        const int fi  = (it << 8) + t;
        const int row = fi >> 4;
        const int c4  = fi & 15;
        *(float4*)(Qs + row * 64 + (c4 << 2)) =
            *(const float4*)(qkv + (size_t)(q0 + row) * QKV_N + qcol + (c4 << 2));
    }

    float m[4], l[4], acc[4][4];
#pragma unroll
    for (int i = 0; i < 4; ++i) {
        m[i] = -1e30f; l[i] = 0.f;
#pragma unroll
        for (int j = 0; j < 4; ++j) acc[i][j] = 0.f;
    }

    const float SCALE = 0.125f;   // HD^-0.5

    for (int kt = 0; kt <= qt; ++kt) {
        const int k0 = kt << 6;

        __syncthreads();   // previous iteration's P/V reads done
        // Load K (swizzled) and V (linear)
#pragma unroll
        for (int it = 0; it < 4; ++it) {
            const int fi  = (it << 8) + t;
            const int row = fi >> 4;
            const int c4  = fi & 15;
            const int c4s = c4 ^ ((row >> 2) & 7);
            *(float4*)(Ks + row * 64 + (c4s << 2)) =
                *(const float4*)(qkv + (size_t)(k0 + row) * QKV_N + kcol + (c4 << 2));
            *(float4*)(Vs + row * 64 + (c4 << 2)) =
                *(const float4*)(qkv + (size_t)(k0 + row) * QKV_N + vcol + (c4 << 2));
        }
        __syncthreads();

        // Scores: s[i][j] = Q[tq*4+i] . K[tn*4+j]
        float s[4][4];
#pragma unroll
        for (int i = 0; i < 4; ++i)
#pragma unroll
            for (int j = 0; j < 4; ++j) s[i][j] = 0.f;

#pragma unroll
        for (int d4 = 0; d4 < 16; ++d4) {
            float4 qv[4], kv[4];
#pragma unroll
            for (int i = 0; i < 4; ++i)
                qv[i] = *(const float4*)(Qs + ((tq * 4 + i) << 6) + (d4 << 2));
            const int c4s = d4 ^ (tn & 7);
#pragma unroll
            for (int j = 0; j < 4; ++j)
                kv[j] = *(const float4*)(Ks + ((tn * 4 + j) << 6) + (c4s << 2));
#pragma unroll
            for (int i = 0; i < 4; ++i)
#pragma unroll
                for (int j = 0; j < 4; ++j)
                    s[i][j] += qv[i].x * kv[j].x + qv[i].y * kv[j].y +
                               qv[i].z * kv[j].z + qv[i].w * kv[j].w;
        }

        // Scale + causal mask (only the diagonal tile needs masking)
        const bool diag = (kt == qt);
#pragma unroll
        for (int i = 0; i < 4; ++i)
#pragma unroll
            for (int j = 0; j < 4; ++j) {
                float v = s[i][j] * SCALE;
                if (diag && (k0 + tn * 4 + j > q0 + tq * 4 + i)) v = -1e30f;
                s[i][j] = v;
            }

        // Online softmax update (row stats shared across the 16 tn lanes)
#pragma unroll
        for (int i = 0; i < 4; ++i) {
            float mx = fmaxf(fmaxf(s[i][0], s[i][1]), fmaxf(s[i][2], s[i][3]));
#pragma unroll
            for (int off = 8; off; off >>= 1)
                mx = fmaxf(mx, __shfl_xor_sync(0xffffffffu, mx, off, 16));
            const float mn = fmaxf(m[i], mx);
            const float cs = expf(m[i] - mn);
            float sum = 0.f;
#pragma unroll
            for (int j = 0; j < 4; ++j) {
                s[i][j] = expf(s[i][j] - mn);
                sum += s[i][j];
            }
#pragma unroll
            for (int off = 8; off; off >>= 1)
                sum += __shfl_xor_sync(0xffffffffu, sum, off, 16);
            l[i] = l[i] * cs + sum;
            m[i] = mn;
            acc[i][0] *= cs; acc[i][1] *= cs; acc[i][2] *= cs; acc[i][3] *= cs;
        }

        __syncthreads();   // everyone done reading Ks
        // Write P into the K buffer (linear layout)
#pragma unroll
        for (int i = 0; i < 4; ++i)
            *(float4*)(Ks + ((tq * 4 + i) << 6) + (tn << 2)) =
                make_float4(s[i][0], s[i][1], s[i][2], s[i][3]);
        __syncthreads();

        // acc += P @ V  (tn now indexes output dims)
#pragma unroll 8
        for (int k = 0; k < 64; ++k) {
            const float4 vv = *(const float4*)(Vs + (k << 6) + (tn << 2));
#pragma unroll
            for (int i = 0; i < 4; ++i) {
                const float pk = Ks[((tq * 4 + i) << 6) + k];
                acc[i][0] += pk * vv.x; acc[i][1] += pk * vv.y;
                acc[i][2] += pk * vv.z; acc[i][3] += pk * vv.w;
            }
        }
    }

    // Epilogue: fold the sink into the denominator and normalize
    const float snk = sinks[h];
#pragma unroll
    for (int i = 0; i < 4; ++i) {
        const float mf    = fmaxf(m[i], snk);
        const float c     = expf(m[i] - mf);
        const float denom = l[i] * c + expf(snk - mf);
        const float inv   = c / denom;
        const int row     = q0 + tq * 4 + i;
        *(float4*)(obuf + (size_t)row * OD + (h << 6) + (tn << 2)) =
            make_float4(acc[i][0] * inv, acc[i][1] * inv,
                        acc[i][2] * inv, acc[i][3] * inv);
    }
}

// ---------------------------------------------------------------------------
extern "C" void kernel_launch(void* const* d_in, const int* in_sizes, int n_in,
                              void* d_out, int out_size)
{
    const int*   positions = (const int*)  d_in[0];
    const float* hidden    = (const float*)d_in[1];
    const float* qkv_w     = (const float*)d_in[2];
    const float* o_w       = (const float*)d_in[3];
    const float* sinks     = (const float*)d_in[4];
    float*       out       = (float*)d_out;

    void* p;
    cudaGetSymbolAddress(&p, g_qkv);
    float* qkvbuf = (float*)p;
    cudaGetSymbolAddress(&p, g_attn);
    float* attnbuf = (float*)p;

    // 1) QKV projection: (1024 x 2880) @ (5120 x 2880)^T -> (1024 x 5120)
    sgemm_nt<<<dim3(QKV_N / 128, S / 128), 256>>>(hidden, qkv_w, qkvbuf, S, QKV_N, H);

    // 2) RoPE on q and k, in place
    {
        const int total = S * (NH + NKV) * (HD / 2);
        rope_kernel<<<(total + 255) / 256, 256>>>(qkvbuf, positions);
    }

    // 3) Flash attention with sinks
    attn_kernel<<<dim3(S / 64, NH), 256>>>(qkvbuf, sinks, attnbuf);

    // 4) Output projection: (1024 x 4096) @ (2880 x 4096)^T -> (1024 x 2880)
    sgemm_nt<<<dim3((H + 127) / 128, S / 128), 256>>>(attnbuf, o_w, out, S, H, OD);
}

// round 4
// speedup vs baseline: 2.2942x; 2.2942x over previous
#include <cuda_runtime.h>
#include <cstdint>
#include <math.h>

// Problem constants
static constexpr int S   = 1024;
static constexpr int H   = 2880;
static constexpr int NH  = 64;
static constexpr int NKV = 8;
static constexpr int HD  = 64;
static constexpr int QKV_N = (NH + 2 * NKV) * HD;   // 5120
static constexpr int OD    = NH * HD;               // 4096

// Scratch (allocation-free rule: __device__ globals)
__device__ __align__(16) float g_qkv [S * QKV_N];   // 20 MB
__device__ __align__(16) float g_attn[S * OD];      // 16 MB

// ---------------------------------------------------------------------------
// TF32 tensor-core GEMM:  C[M,N] = A[M,K] @ B[N,K]^T
// A row-major (K contiguous), B row-major (K contiguous) == B^T col-major.
// 128x128 block tile, BK=16, 256 threads (8 warps, 4x2), warp tile 32x64,
// mma.sync.aligned.m16n8k8.row.col.f32.tf32.tf32.f32, cp.async double buffer.
// Requires M%128==0, K%16==0; N guarded (zero-filled B rows, guarded stores).
// ---------------------------------------------------------------------------
static constexpr int BM = 128, BN = 128, BK = 16;
static constexpr int SST = 20;                  // padded smem row stride (floats)

__device__ __forceinline__ uint32_t f2tf32(float f) {
    uint32_t r;
    asm volatile("cvt.rna.tf32.f32 %0, %1;" : "=r"(r) : "f"(f));
    return r;
}

__device__ __forceinline__ void cp16(float* s, const float* g, bool pred) {
    uint32_t sa = (uint32_t)__cvta_generic_to_shared(s);
    int sz = pred ? 16 : 0;
    asm volatile("cp.async.cg.shared.global [%0], [%1], 16, %2;"
                 :: "r"(sa), "l"(g), "r"(sz));
}

__global__ __launch_bounds__(256, 2) void gemm_tf32(
    const float* __restrict__ A, const float* __restrict__ B,
    float* __restrict__ C, int M, int N, int K)
{
    __shared__ float As[2][BM * SST];
    __shared__ float Bs[2][BN * SST];

    const int t    = threadIdx.x;
    const int lane = t & 31;
    const int warp = t >> 5;
    const int wRow = warp >> 1;          // 0..3 -> 32-row slab
    const int wCol = warp & 1;           // 0..1 -> 64-col slab
    const int bm   = blockIdx.y * BM;
    const int bn   = blockIdx.x * BN;

    const int gr = lane >> 2;            // 0..7
    const int kc = lane & 3;             // 0..3

    float acc[2][8][4];
#pragma unroll
    for (int i = 0; i < 2; ++i)
#pragma unroll
        for (int j = 0; j < 8; ++j)
#pragma unroll
            for (int r = 0; r < 4; ++r) acc[i][j][r] = 0.f;

    // tile loader: 512 float4 chunks per matrix, 2 per thread
    auto load_tile = [&](int buf, int kt) {
#pragma unroll
        for (int i = 0; i < 2; ++i) {
            const int ch  = t + 256 * i;
            const int row = ch >> 2;
            const int c4  = (ch & 3) << 2;
            cp16(&As[buf][row * SST + c4],
                 A + (size_t)(bm + row) * K + kt + c4, true);
            cp16(&Bs[buf][row * SST + c4],
                 B + (size_t)(bn + row) * K + kt + c4, (bn + row) < N);
        }
    };

    int buf = 0;
    load_tile(buf, 0);
    asm volatile("cp.async.commit_group;");

    for (int kt = 0; kt < K; kt += BK) {
        const int nxt = kt + BK;
        if (nxt < K) {
            load_tile(buf ^ 1, nxt);
            asm volatile("cp.async.commit_group;");
            asm volatile("cp.async.wait_group 1;");
        } else {
            asm volatile("cp.async.wait_group 0;");
        }
        __syncthreads();

        const float* as = As[buf];
        const float* bs = Bs[buf];
#pragma unroll
        for (int k8 = 0; k8 < BK; k8 += 8) {
            uint32_t af[2][4], bf[8][2];
#pragma unroll
            for (int i = 0; i < 2; ++i) {
                const int rb = wRow * 32 + i * 16;
                af[i][0] = f2tf32(as[(rb + gr)     * SST + k8 + kc]);
                af[i][1] = f2tf32(as[(rb + gr + 8) * SST + k8 + kc]);
                af[i][2] = f2tf32(as[(rb + gr)     * SST + k8 + kc + 4]);
                af[i][3] = f2tf32(as[(rb + gr + 8) * SST + k8 + kc + 4]);
            }
#pragma unroll
            for (int j = 0; j < 8; ++j) {
                const int cb = wCol * 64 + j * 8;
                bf[j][0] = f2tf32(bs[(cb + gr) * SST + k8 + kc]);
                bf[j][1] = f2tf32(bs[(cb + gr) * SST + k8 + kc + 4]);
            }
#pragma unroll
            for (int i = 0; i < 2; ++i)
#pragma unroll
                for (int j = 0; j < 8; ++j) {
                    asm volatile(
                        "mma.sync.aligned.m16n8k8.row.col.f32.tf32.tf32.f32 "
                        "{%0,%1,%2,%3}, {%4,%5,%6,%7}, {%8,%9}, {%0,%1,%2,%3};"
                        : "+f"(acc[i][j][0]), "+f"(acc[i][j][1]),
                          "+f"(acc[i][j][2]), "+f"(acc[i][j][3])
                        : "r"(af[i][0]), "r"(af[i][1]), "r"(af[i][2]), "r"(af[i][3]),
                          "r"(bf[j][0]), "r"(bf[j][1]));
                }
        }
        __syncthreads();
        buf ^= 1;
    }

    // Epilogue
#pragma unroll
    for (int i = 0; i < 2; ++i) {
        const int row = bm + wRow * 32 + i * 16 + gr;
#pragma unroll
        for (int j = 0; j < 8; ++j) {
            const int col = bn + wCol * 64 + j * 8 + kc * 2;
            if (col < N) {
                *(float2*)(C + (size_t)row * N + col) =
                    make_float2(acc[i][j][0], acc[i][j][1]);
                *(float2*)(C + (size_t)(row + 8) * N + col) =
                    make_float2(acc[i][j][2], acc[i][j][3]);
            }
        }
    }
}

// ---------------------------------------------------------------------------
// RoPE on q (heads 0..63) and k (heads 64..71), in place in g_qkv.
// ---------------------------------------------------------------------------
__global__ void rope_kernel(float* __restrict__ qkv, const int* __restrict__ positions)
{
    const int id = blockIdx.x * blockDim.x + threadIdx.x;
    const int total = S * (NH + NKV) * (HD / 2);
    if (id >= total) return;

    const int p    = id & 31;                 // pair index 0..31
    const int head = (id >> 5) % (NH + NKV);  // 0..71
    const int s    = id / (32 * (NH + NKV));

    const int col = (head < NH) ? head * HD : NH * HD + (head - NH) * HD;
    float* base = qkv + (size_t)s * QKV_N + col;

    const float x1 = base[p];
    const float x2 = base[p + 32];

    const float freq = 1.0f / powf(10000.0f, (float)p * (1.0f / 32.0f));
    const float ang  = (float)positions[s] * freq;
    double sd, cd;
    sincos((double)ang, &sd, &cd);
    const float c = (float)cd, sn = (float)sd;

    base[p]      = x1 * c - x2 * sn;
    base[p + 32] = x2 * c + x1 * sn;
}

// ---------------------------------------------------------------------------
// Flash attention with sink + causal mask (fp32 SIMT, unchanged from R2).
// ---------------------------------------------------------------------------
__global__ __launch_bounds__(256) void attn_kernel(
    const float* __restrict__ qkv, const float* __restrict__ sinks,
    float* __restrict__ obuf)
{
    __shared__ float Qs[64 * 64];
    __shared__ float Ks[64 * 64];   // aliased as P after the score phase
    __shared__ float Vs[64 * 64];

    const int t   = threadIdx.x;
    const int qt  = blockIdx.x;      // query tile 0..15
    const int h   = blockIdx.y;      // head 0..63
    const int kvh = h >> 3;
    const int q0  = qt << 6;
    const int tq  = t >> 4;          // 0..15
    const int tn  = t & 15;          // 0..15

    const int qcol = h << 6;
    const int kcol = NH * HD + (kvh << 6);
    const int vcol = NH * HD + NKV * HD + (kvh << 6);

#pragma unroll
    for (int it = 0; it < 4; ++it) {
        const int fi  = (it << 8) + t;
        const int row = fi >> 4;
        const int c4  = fi & 15;
        *(float4*)(Qs + row * 64 + (c4 << 2)) =
            *(const float4*)(qkv + (size_t)(q0 + row) * QKV_N + qcol + (c4 << 2));
    }

    float m[4], l[4], acc[4][4];
#pragma unroll
    for (int i = 0; i < 4; ++i) {
        m[i] = -1e30f; l[i] = 0.f;
#pragma unroll
        for (int j = 0; j < 4; ++j) acc[i][j] = 0.f;
    }

    const float SCALE = 0.125f;

    for (int kt = 0; kt <= qt; ++kt) {
        const int k0 = kt << 6;

        __syncthreads();
#pragma unroll
        for (int it = 0; it < 4; ++it) {
            const int fi  = (it << 8) + t;
            const int row = fi >> 4;
            const int c4  = fi & 15;
            const int c4s = c4 ^ ((row >> 2) & 7);
            *(float4*)(Ks + row * 64 + (c4s << 2)) =
                *(const float4*)(qkv + (size_t)(k0 + row) * QKV_N + kcol + (c4 << 2));
            *(float4*)(Vs + row * 64 + (c4 << 2)) =
                *(const float4*)(qkv + (size_t)(k0 + row) * QKV_N + vcol + (c4 << 2));
        }
        __syncthreads();

        float s[4][4];
#pragma unroll
        for (int i = 0; i < 4; ++i)
#pragma unroll
            for (int j = 0; j < 4; ++j) s[i][j] = 0.f;

#pragma unroll
        for (int d4 = 0; d4 < 16; ++d4) {
            float4 qv[4], kv[4];
#pragma unroll
            for (int i = 0; i < 4; ++i)
                qv[i] = *(const float4*)(Qs + ((tq * 4 + i) << 6) + (d4 << 2));
            const int c4s = d4 ^ (tn & 7);
#pragma unroll
            for (int j = 0; j < 4; ++j)
                kv[j] = *(const float4*)(Ks + ((tn * 4 + j) << 6) + (c4s << 2));
#pragma unroll
            for (int i = 0; i < 4; ++i)
#pragma unroll
                for (int j = 0; j < 4; ++j)
                    s[i][j] += qv[i].x * kv[j].x + qv[i].y * kv[j].y +
                               qv[i].z * kv[j].z + qv[i].w * kv[j].w;
        }

        const bool diag = (kt == qt);
#pragma unroll
        for (int i = 0; i < 4; ++i)
#pragma unroll
            for (int j = 0; j < 4; ++j) {
                float v = s[i][j] * SCALE;
                if (diag && (k0 + tn * 4 + j > q0 + tq * 4 + i)) v = -1e30f;
                s[i][j] = v;
            }

#pragma unroll
        for (int i = 0; i < 4; ++i) {
            float mx = fmaxf(fmaxf(s[i][0], s[i][1]), fmaxf(s[i][2], s[i][3]));
#pragma unroll
            for (int off = 8; off; off >>= 1)
                mx = fmaxf(mx, __shfl_xor_sync(0xffffffffu, mx, off, 16));
            const float mn = fmaxf(m[i], mx);
            const float cs = expf(m[i] - mn);
            float sum = 0.f;
#pragma unroll
            for (int j = 0; j < 4; ++j) {
                s[i][j] = expf(s[i][j] - mn);
                sum += s[i][j];
            }
#pragma unroll
            for (int off = 8; off; off >>= 1)
                sum += __shfl_xor_sync(0xffffffffu, sum, off, 16);
            l[i] = l[i] * cs + sum;
            m[i] = mn;
            acc[i][0] *= cs; acc[i][1] *= cs; acc[i][2] *= cs; acc[i][3] *= cs;
        }

        __syncthreads();
#pragma unroll
        for (int i = 0; i < 4; ++i)
            *(float4*)(Ks + ((tq * 4 + i) << 6) + (tn << 2)) =
                make_float4(s[i][0], s[i][1], s[i][2], s[i][3]);
        __syncthreads();

#pragma unroll 8
        for (int k = 0; k < 64; ++k) {
            const float4 vv = *(const float4*)(Vs + (k << 6) + (tn << 2));
#pragma unroll
            for (int i = 0; i < 4; ++i) {
                const float pk = Ks[((tq * 4 + i) << 6) + k];
                acc[i][0] += pk * vv.x; acc[i][1] += pk * vv.y;
                acc[i][2] += pk * vv.z; acc[i][3] += pk * vv.w;
            }
        }
    }

    const float snk = sinks[h];
#pragma unroll
    for (int i = 0; i < 4; ++i) {
        const float mf    = fmaxf(m[i], snk);
        const float c     = expf(m[i] - mf);
        const float denom = l[i] * c + expf(snk - mf);
        const float inv   = c / denom;
        const int row     = q0 + tq * 4 + i;
        *(float4*)(obuf + (size_t)row * OD + (h << 6) + (tn << 2)) =
            make_float4(acc[i][0] * inv, acc[i][1] * inv,
                        acc[i][2] * inv, acc[i][3] * inv);
    }
}

// ---------------------------------------------------------------------------
extern "C" void kernel_launch(void* const* d_in, const int* in_sizes, int n_in,
                              void* d_out, int out_size)
{
    const int*   positions = (const int*)  d_in[0];
    const float* hidden    = (const float*)d_in[1];
    const float* qkv_w     = (const float*)d_in[2];
    const float* o_w       = (const float*)d_in[3];
    const float* sinks     = (const float*)d_in[4];
    float*       out       = (float*)d_out;

    void* p;
    cudaGetSymbolAddress(&p, g_qkv);
    float* qkvbuf = (float*)p;
    cudaGetSymbolAddress(&p, g_attn);
    float* attnbuf = (float*)p;

    // 1) QKV projection: (1024 x 2880) @ (5120 x 2880)^T -> (1024 x 5120)
    gemm_tf32<<<dim3(QKV_N / BN, S / BM), 256>>>(hidden, qkv_w, qkvbuf, S, QKV_N, H);

    // 2) RoPE on q and k, in place
    {
        const int total = S * (NH + NKV) * (HD / 2);
        rope_kernel<<<(total + 255) / 256, 256>>>(qkvbuf, positions);
    }

    // 3) Flash attention with sinks
    attn_kernel<<<dim3(S / 64, NH), 256>>>(qkvbuf, sinks, attnbuf);

    // 4) Output projection: (1024 x 4096) @ (2880 x 4096)^T -> (1024 x 2880)
    gemm_tf32<<<dim3((H + BN - 1) / BN, S / BM), 256>>>(attnbuf, o_w, out, S, H, OD);
}